// round 1
// baseline (speedup 1.0000x reference)
#include <cuda_runtime.h>
#include <math.h>

#define NB   8
#define ND   512
#define NDIM 2
#define NCH  3
#define NMIX 4
#define HD   128

// feature_xc scratch: [b][a][k][m], m contiguous (float4-friendly)
__device__ float g_feat[NB * ND * NCH * NMIX];

__device__ __forceinline__ float ex2_approx(float x) {
    float r;
    asm("ex2.approx.ftz.f32 %0, %1;" : "=f"(r) : "f"(x));
    return r;
}

// ---------------------------------------------------------------------------
// Kernel 1: fused pairwise spectral-mixture kernel + contraction with yc.
// Grid: 96 combos (b,k,m) x 8 a-slices = 768 blocks, 64 threads each.
// Each block: precompute c-side arrays in smem (O(N)), then each thread
// owns one 'a' and reduces over all 512 'c'. Inner loop: 6 FMA + 1 EX2 + 2 LDS.
// ---------------------------------------------------------------------------
__global__ __launch_bounds__(64) void k1_feature(
    const float* __restrict__ xc, const float* __restrict__ yc,
    const float* __restrict__ mu, const float* __restrict__ istd)
{
    // per-c pack: {u0, u1, -A*e_c, y*cos}, plus y*sin separate
    __shared__ float4 spack[ND];
    __shared__ float  sS[ND];

    const int bx    = blockIdx.x;
    const int slice = bx & 7;        // 0..7  (a-slice of 64)
    const int combo = bx >> 3;       // 0..95
    const int m     = combo & 3;
    const int bk    = combo >> 2;    // b*3 + k
    const int k     = bk % 3;
    const int b     = bk / 3;

    // A = 0.5*(2pi)^2 * log2(e)
    const float AL2 = 19.739208802178716f * 1.4426950408889634f;
    const float PI2f = 6.2831853071795864f;

    const float is0 = istd[m * 2 + 0], is1 = istd[m * 2 + 1];
    const float m0  = mu[m * 2 + 0],  m1  = mu[m * 2 + 1];

    const int tid = threadIdx.x;

    // ---- c-side precompute (broadcast data for the whole block) ----
    for (int c = tid; c < ND; c += 64) {
        const int gi = b * ND + c;
        float x0 = xc[gi * 6 + k];          // ((gi*2+0)*3 + k)
        float x1 = xc[gi * 6 + 3 + k];      // ((gi*2+1)*3 + k)
        float y  = yc[gi * 3 + k];
        float u0 = x0 * is0, u1 = x1 * is1;
        float e  = u0 * u0 + u1 * u1;
        float p  = x0 * m0 + x1 * m1;
        p -= rintf(p);                      // range-reduce for MUFU accuracy
        float s, cph;
        __sincosf(PI2f * p, &s, &cph);
        spack[c] = make_float4(u0, u1, -AL2 * e, y * cph);
        sS[c]    = y * s;
    }
    __syncthreads();

    // ---- a-side per-thread values ----
    const int a  = slice * 64 + tid;
    const int ai = b * ND + a;
    float x0 = xc[ai * 6 + k];
    float x1 = xc[ai * 6 + 3 + k];
    float ya = yc[ai * 3 + k];
    float ua0 = x0 * is0, ua1 = x1 * is1;
    float wa0 = 2.0f * AL2 * ua0;
    float wa1 = 2.0f * AL2 * ua1;
    float base = -AL2 * (ua0 * ua0 + ua1 * ua1);   // kept INSIDE exp2 arg (<=0 total)
    float p = x0 * m0 + x1 * m1;
    p -= rintf(p);
    float sa, ca;
    __sincosf(PI2f * p, &sa, &ca);

    // ---- main reduction over c ----
    float acc = 0.0f;
#pragma unroll 8
    for (int c = 0; c < ND; c++) {
        float4 v = spack[c];
        float S  = sS[c];
        float t = fmaf(wa0, v.x, v.z);     // wa0*uc0 + (-A*e_c)
        t = fmaf(wa1, v.y, t);
        t += base;                          // total arg <= 0 -> no overflow
        float e = ex2_approx(t);
        float q = fmaf(sa, S, ca * v.w);    // cos addition theorem
        acc = fmaf(e, q, acc);
    }
    acc += 0.0001f * ya;                    // ZITTER * eye term

    g_feat[(ai * 3 + k) * 4 + m] = acc;
}

// ---------------------------------------------------------------------------
// Kernel 2: layer1 + mean over a, then the 3 hidden GEMVs + head.
// One block per batch (8 blocks, 384 threads).
// ---------------------------------------------------------------------------
__global__ __launch_bounds__(384) void k2_mlp(
    const float* __restrict__ yc,
    const float* __restrict__ w1, const float* __restrict__ b1,
    const float* __restrict__ w2, const float* __restrict__ b2,
    const float* __restrict__ w3, const float* __restrict__ b3,
    const float* __restrict__ w4, const float* __restrict__ b4,
    const float* __restrict__ w5, const float* __restrict__ b5,
    float* __restrict__ out)
{
    __shared__ float4 sF[ND * NCH];                    // 24 KB
    __shared__ float  sy[ND * NCH];                    // 6 KB
    __shared__ __align__(16) float h0[NCH * HD];       // 384
    __shared__ __align__(16) float h1[HD];
    __shared__ __align__(16) float h2[HD];
    __shared__ __align__(16) float h3[HD];

    const int b   = blockIdx.x;
    const int tid = threadIdx.x;

    const float4* gF = reinterpret_cast<const float4*>(g_feat) + b * ND * NCH;
    for (int i = tid; i < ND * NCH; i += 384) {
        sF[i] = gF[i];
        sy[i] = yc[b * ND * NCH + i];
    }
    __syncthreads();

    // ---- stage A: feat @ w1^T, relu, mean over a ----
    {
        const int k = tid / HD;   // 0..2
        const int j = tid % HD;
        float wj0 = w1[j * 5 + 0], wj1 = w1[j * 5 + 1], wj2 = w1[j * 5 + 2];
        float wj3 = w1[j * 5 + 3], wj4 = w1[j * 5 + 4], bj = b1[j];
        float acc = 0.0f;
#pragma unroll 4
        for (int a = 0; a < ND; a++) {
            float4 f = sF[a * 3 + k];
            float  y = sy[a * 3 + k];
            float v = fmaf(f.x, wj0,
                      fmaf(f.y, wj1,
                      fmaf(f.z, wj2,
                      fmaf(f.w, wj3,
                      fmaf(y,   wj4, bj)))));
            acc += fmaxf(v, 0.0f);
        }
        h0[tid] = acc * (1.0f / (float)ND);
    }
    __syncthreads();

    // ---- stage B: 384 -> 128 ----
    if (tid < HD) {
        float acc = b2[tid];
        const float4* wr = reinterpret_cast<const float4*>(w2 + tid * (NCH * HD));
        const float4* hv = reinterpret_cast<const float4*>(h0);
#pragma unroll
        for (int i = 0; i < (NCH * HD) / 4; i++) {
            float4 w = wr[i]; float4 h = hv[i];
            acc = fmaf(w.x, h.x, fmaf(w.y, h.y, fmaf(w.z, h.z, fmaf(w.w, h.w, acc))));
        }
        h1[tid] = fmaxf(acc, 0.0f);
    }
    __syncthreads();

    // ---- stage C: 128 -> 128 ----
    if (tid < HD) {
        float acc = b3[tid];
        const float4* wr = reinterpret_cast<const float4*>(w3 + tid * HD);
        const float4* hv = reinterpret_cast<const float4*>(h1);
#pragma unroll
        for (int i = 0; i < HD / 4; i++) {
            float4 w = wr[i]; float4 h = hv[i];
            acc = fmaf(w.x, h.x, fmaf(w.y, h.y, fmaf(w.z, h.z, fmaf(w.w, h.w, acc))));
        }
        h2[tid] = fmaxf(acc, 0.0f);
    }
    __syncthreads();

    // ---- stage D: 128 -> 128 ----
    if (tid < HD) {
        float acc = b4[tid];
        const float4* wr = reinterpret_cast<const float4*>(w4 + tid * HD);
        const float4* hv = reinterpret_cast<const float4*>(h2);
#pragma unroll
        for (int i = 0; i < HD / 4; i++) {
            float4 w = wr[i]; float4 h = hv[i];
            acc = fmaf(w.x, h.x, fmaf(w.y, h.y, fmaf(w.z, h.z, fmaf(w.w, h.w, acc))));
        }
        h3[tid] = fmaxf(acc, 0.0f);
    }
    __syncthreads();

    // ---- stage E: 128 -> 12 head ----
    if (tid < NCH * NMIX) {
        float acc = b5[tid];
        const float4* wr = reinterpret_cast<const float4*>(w5 + tid * HD);
        const float4* hv = reinterpret_cast<const float4*>(h3);
#pragma unroll
        for (int i = 0; i < HD / 4; i++) {
            float4 w = wr[i]; float4 h = hv[i];
            acc = fmaf(w.x, h.x, fmaf(w.y, h.y, fmaf(w.z, h.z, fmaf(w.w, h.w, acc))));
        }
        out[b * (NCH * NMIX) + tid] = acc;
    }
}

extern "C" void kernel_launch(void* const* d_in, const int* in_sizes, int n_in,
                              void* d_out, int out_size)
{
    (void)in_sizes; (void)n_in; (void)out_size;
    const float* xc   = (const float*)d_in[0];
    const float* yc   = (const float*)d_in[1];
    const float* mu   = (const float*)d_in[2];
    const float* istd = (const float*)d_in[3];
    const float* w1   = (const float*)d_in[4];
    const float* b1   = (const float*)d_in[5];
    const float* w2   = (const float*)d_in[6];
    const float* b2   = (const float*)d_in[7];
    const float* w3   = (const float*)d_in[8];
    const float* b3   = (const float*)d_in[9];
    const float* w4   = (const float*)d_in[10];
    const float* b4   = (const float*)d_in[11];
    const float* w5   = (const float*)d_in[12];
    const float* b5   = (const float*)d_in[13];
    float* out        = (float*)d_out;

    k1_feature<<<96 * 8, 64>>>(xc, yc, mu, istd);
    k2_mlp<<<NB, 384>>>(yc, w1, b1, w2, b2, w3, b3, w4, b4, w5, b5, out);
}

// round 3
// speedup vs baseline: 1.1854x; 1.1854x over previous
#include <cuda_runtime.h>
#include <math.h>

#define NB   8
#define ND   512
#define NDIM 2
#define NCH  3
#define NMIX 4
#define HD   128

// feature_xc scratch: [b][a][k][m], m contiguous (float4-friendly)
__device__ float g_feat[NB * ND * NCH * NMIX];
// h0 scratch: [b][k*128+j]
__device__ float g_h0[NB * NCH * HD];

__device__ __forceinline__ float ex2_approx(float x) {
    float r;
    asm("ex2.approx.ftz.f32 %0, %1;" : "=f"(r) : "f"(x));
    return r;
}

// ---------------------------------------------------------------------------
// Kernel 1: fused pairwise spectral-mixture kernel + contraction with yc.
// Grid: 96 combos (b,k,m) x 8 a-slices = 768 blocks, 64 threads each.
// ---------------------------------------------------------------------------
__global__ __launch_bounds__(64) void k1_feature(
    const float* __restrict__ xc, const float* __restrict__ yc,
    const float* __restrict__ mu, const float* __restrict__ istd)
{
    __shared__ float4 spack[ND];
    __shared__ float  sS[ND];

    const int bx    = blockIdx.x;
    const int slice = bx & 7;        // 0..7  (a-slice of 64)
    const int combo = bx >> 3;       // 0..95
    const int m     = combo & 3;
    const int bk    = combo >> 2;    // b*3 + k
    const int k     = bk % 3;
    const int b     = bk / 3;

    // A = 0.5*(2pi)^2 * log2(e)
    const float AL2  = 19.739208802178716f * 1.4426950408889634f;
    const float PI2f = 6.2831853071795864f;

    const float is0 = istd[m * 2 + 0], is1 = istd[m * 2 + 1];
    const float m0  = mu[m * 2 + 0],  m1  = mu[m * 2 + 1];

    const int tid = threadIdx.x;

    // ---- a-side loads issued early (overlap with precompute + barrier) ----
    const int a  = slice * 64 + tid;
    const int ai = b * ND + a;
    const float ax0 = xc[ai * 6 + k];
    const float ax1 = xc[ai * 6 + 3 + k];
    const float ya  = yc[ai * 3 + k];

    // ---- c-side precompute ----
    for (int c = tid; c < ND; c += 64) {
        const int gi = b * ND + c;
        float x0 = xc[gi * 6 + k];
        float x1 = xc[gi * 6 + 3 + k];
        float y  = yc[gi * 3 + k];
        float u0 = x0 * is0, u1 = x1 * is1;
        float e  = u0 * u0 + u1 * u1;
        float p  = x0 * m0 + x1 * m1;
        p -= rintf(p);
        float s, cph;
        __sincosf(PI2f * p, &s, &cph);
        spack[c] = make_float4(u0, u1, -AL2 * e, y * cph);
        sS[c]    = y * s;
    }

    // ---- a-side per-thread values ----
    float ua0 = ax0 * is0, ua1 = ax1 * is1;
    float wa0 = 2.0f * AL2 * ua0;
    float wa1 = 2.0f * AL2 * ua1;
    float base = -AL2 * (ua0 * ua0 + ua1 * ua1);
    float p = ax0 * m0 + ax1 * m1;
    p -= rintf(p);
    float sa, ca;
    __sincosf(PI2f * p, &sa, &ca);

    __syncthreads();

    float acc = 0.0f;
#pragma unroll 8
    for (int c = 0; c < ND; c++) {
        float4 v = spack[c];
        float S  = sS[c];
        float t = fmaf(wa0, v.x, v.z);
        t = fmaf(wa1, v.y, t);
        t += base;
        float e = ex2_approx(t);
        float q = fmaf(sa, S, ca * v.w);
        acc = fmaf(e, q, acc);
    }
    acc += 0.0001f * ya;

    g_feat[(ai * 3 + k) * 4 + m] = acc;
}

// ---------------------------------------------------------------------------
// Kernel 2a: layer-1 + relu + mean over a, one WARP per output (b, k*128+j).
// Grid: 384 blocks x 256 threads = 3072 warps = 8 batches x 384 outputs.
// ---------------------------------------------------------------------------
__global__ __launch_bounds__(256) void k2a_layer1(
    const float* __restrict__ yc,
    const float* __restrict__ w1, const float* __restrict__ b1)
{
    const int gw   = blockIdx.x * 8 + (threadIdx.x >> 5);  // 0..3071
    const int lane = threadIdx.x & 31;
    const int b    = gw / (NCH * HD);
    const int o    = gw % (NCH * HD);      // k*128 + j
    const int k    = o / HD;
    const int j    = o % HD;

    // lane-uniform weight loads (broadcast)
    const float wj0 = w1[j * 5 + 0], wj1 = w1[j * 5 + 1], wj2 = w1[j * 5 + 2];
    const float wj3 = w1[j * 5 + 3], wj4 = w1[j * 5 + 4], bj = b1[j];

    const float4* gF = reinterpret_cast<const float4*>(g_feat);

    float acc = 0.0f;
#pragma unroll
    for (int i = 0; i < ND / 32; i++) {
        const int a  = i * 32 + lane;
        const int gi = (b * ND + a) * 3 + k;
        float4 f = gF[gi];
        float  y = yc[gi];
        float v = fmaf(f.x, wj0,
                  fmaf(f.y, wj1,
                  fmaf(f.z, wj2,
                  fmaf(f.w, wj3,
                  fmaf(y,   wj4, bj)))));
        acc += fmaxf(v, 0.0f);
    }
    // warp reduce
#pragma unroll
    for (int s = 16; s > 0; s >>= 1)
        acc += __shfl_xor_sync(0xFFFFFFFFu, acc, s);

    if (lane == 0)
        g_h0[b * (NCH * HD) + o] = acc * (1.0f / (float)ND);
}

// ---------------------------------------------------------------------------
// Kernel 2b: the 3 hidden GEMVs + head. One block per batch, 128 threads.
// ---------------------------------------------------------------------------
__global__ __launch_bounds__(128) void k2b_mlp(
    const float* __restrict__ w2, const float* __restrict__ b2,
    const float* __restrict__ w3, const float* __restrict__ b3,
    const float* __restrict__ w4, const float* __restrict__ b4,
    const float* __restrict__ w5, const float* __restrict__ b5,
    float* __restrict__ out)
{
    __shared__ __align__(16) float h0[NCH * HD];
    __shared__ __align__(16) float h1[HD];
    __shared__ __align__(16) float h2[HD];
    __shared__ __align__(16) float h3[HD];

    const int b   = blockIdx.x;
    const int tid = threadIdx.x;

    for (int i = tid; i < NCH * HD; i += 128)
        h0[i] = g_h0[b * (NCH * HD) + i];
    __syncthreads();

    // ---- 384 -> 128 ----
    {
        float a0 = b2[tid], a1 = 0.0f;
        const float4* wr = reinterpret_cast<const float4*>(w2 + tid * (NCH * HD));
        const float4* hv = reinterpret_cast<const float4*>(h0);
#pragma unroll
        for (int i = 0; i < (NCH * HD) / 8; i++) {
            float4 w = wr[2 * i],     h = hv[2 * i];
            float4 w2_ = wr[2 * i + 1], h2_ = hv[2 * i + 1];
            a0 = fmaf(w.x, h.x, fmaf(w.y, h.y, fmaf(w.z, h.z, fmaf(w.w, h.w, a0))));
            a1 = fmaf(w2_.x, h2_.x, fmaf(w2_.y, h2_.y, fmaf(w2_.z, h2_.z, fmaf(w2_.w, h2_.w, a1))));
        }
        h1[tid] = fmaxf(a0 + a1, 0.0f);
    }
    __syncthreads();

    // ---- 128 -> 128 ----
    {
        float a0 = b3[tid], a1 = 0.0f;
        const float4* wr = reinterpret_cast<const float4*>(w3 + tid * HD);
        const float4* hv = reinterpret_cast<const float4*>(h1);
#pragma unroll
        for (int i = 0; i < HD / 8; i++) {
            float4 w = wr[2 * i],     h = hv[2 * i];
            float4 w2_ = wr[2 * i + 1], h2_ = hv[2 * i + 1];
            a0 = fmaf(w.x, h.x, fmaf(w.y, h.y, fmaf(w.z, h.z, fmaf(w.w, h.w, a0))));
            a1 = fmaf(w2_.x, h2_.x, fmaf(w2_.y, h2_.y, fmaf(w2_.z, h2_.z, fmaf(w2_.w, h2_.w, a1))));
        }
        h2[tid] = fmaxf(a0 + a1, 0.0f);
    }
    __syncthreads();

    // ---- 128 -> 128 ----
    {
        float a0 = b4[tid], a1 = 0.0f;
        const float4* wr = reinterpret_cast<const float4*>(w4 + tid * HD);
        const float4* hv = reinterpret_cast<const float4*>(h2);
#pragma unroll
        for (int i = 0; i < HD / 8; i++) {
            float4 w = wr[2 * i],     h = hv[2 * i];
            float4 w2_ = wr[2 * i + 1], h2_ = hv[2 * i + 1];
            a0 = fmaf(w.x, h.x, fmaf(w.y, h.y, fmaf(w.z, h.z, fmaf(w.w, h.w, a0))));
            a1 = fmaf(w2_.x, h2_.x, fmaf(w2_.y, h2_.y, fmaf(w2_.z, h2_.z, fmaf(w2_.w, h2_.w, a1))));
        }
        h3[tid] = fmaxf(a0 + a1, 0.0f);
    }
    __syncthreads();

    // ---- 128 -> 12 head ----
    if (tid < NCH * NMIX) {
        float a0 = b5[tid], a1 = 0.0f;
        const float4* wr = reinterpret_cast<const float4*>(w5 + tid * HD);
        const float4* hv = reinterpret_cast<const float4*>(h3);
#pragma unroll
        for (int i = 0; i < HD / 8; i++) {
            float4 w = wr[2 * i],     h = hv[2 * i];
            float4 w2_ = wr[2 * i + 1], h2_ = hv[2 * i + 1];
            a0 = fmaf(w.x, h.x, fmaf(w.y, h.y, fmaf(w.z, h.z, fmaf(w.w, h.w, a0))));
            a1 = fmaf(w2_.x, h2_.x, fmaf(w2_.y, h2_.y, fmaf(w2_.z, h2_.z, fmaf(w2_.w, h2_.w, a1))));
        }
        out[b * (NCH * NMIX) + tid] = a0 + a1;
    }
}

extern "C" void kernel_launch(void* const* d_in, const int* in_sizes, int n_in,
                              void* d_out, int out_size)
{
    (void)in_sizes; (void)n_in; (void)out_size;
    const float* xc   = (const float*)d_in[0];
    const float* yc   = (const float*)d_in[1];
    const float* mu   = (const float*)d_in[2];
    const float* istd = (const float*)d_in[3];
    const float* w1   = (const float*)d_in[4];
    const float* b1   = (const float*)d_in[5];
    const float* w2   = (const float*)d_in[6];
    const float* b2   = (const float*)d_in[7];
    const float* w3   = (const float*)d_in[8];
    const float* b3   = (const float*)d_in[9];
    const float* w4   = (const float*)d_in[10];
    const float* b4   = (const float*)d_in[11];
    const float* w5   = (const float*)d_in[12];
    const float* b5   = (const float*)d_in[13];
    float* out        = (float*)d_out;

    k1_feature<<<96 * 8, 64>>>(xc, yc, mu, istd);
    k2a_layer1<<<NB * NCH * HD / 8, 256>>>(yc, w1, b1);
    k2b_mlp<<<NB, 128>>>(w2, b2, w3, b3, w4, b4, w5, b5, out);
}